// round 3
// baseline (speedup 1.0000x reference)
#include <cuda_runtime.h>
#include <math.h>

// Problem constants
// B=2, S=2048, T=4096 tokens, D_IN=2048, H=16, QK_HEAD=128 (64 nope + 64 rope),
// V_HEAD=128, KV_RANK=512, D_OUT=2048
#define TOKS 4096
#define SEQ  2048

// ---------------------------------------------------------------------------
// Scratch (static __device__ arrays: allocation-free per harness rules)
// ---------------------------------------------------------------------------
__device__ float g_q[(size_t)TOKS * 2048];      // [T,H,128] q (rope applied in place)
__device__ float g_kv[(size_t)TOKS * 576];      // [T,576] raw kv = x@wkv_a
__device__ float g_kvc[(size_t)TOKS * 512];     // [T,512] rms-normed latent
__device__ float g_kpe[(size_t)TOKS * 64];      // [T,64] roped k_pe
__device__ float g_kvdec[(size_t)TOKS * 3072];  // [T,H,192] (k_nope 64 | v 128)
__device__ float g_attn[(size_t)TOKS * 2048];   // [T,H,128] attention output

// ---------------------------------------------------------------------------
// SGEMM: C[M,N] = A[M,K] @ B[K,N], row-major. BM=BN=128, BK=8, 8x8/thread.
// Requirements: M%128==0, K%8==0, N%4==0 (N guarded).
// ---------------------------------------------------------------------------
__global__ __launch_bounds__(256)
void sgemm_kernel(const float* __restrict__ A, const float* __restrict__ B,
                  float* __restrict__ C, int M, int N, int K)
{
    __shared__ float As[8][128];   // transposed: As[k][m]
    __shared__ float Bs[8][128];   // Bs[k][n]

    const int t  = threadIdx.x;
    const int tx = t & 15;
    const int ty = t >> 4;
    const int row0 = blockIdx.y * 128;
    const int col0 = blockIdx.x * 128;

    const int arow = t >> 1;           // 0..127
    const int acol = (t & 1) * 4;      // 0 or 4
    const int brow = t >> 5;           // 0..7
    const int bcol = (t & 31) * 4;     // 0..124

    float acc[8][8];
#pragma unroll
    for (int i = 0; i < 8; i++)
#pragma unroll
        for (int j = 0; j < 8; j++) acc[i][j] = 0.0f;

    const int nkt = K >> 3;
    for (int kt = 0; kt < nkt; kt++) {
        const int k0 = kt << 3;
        // load A tile (always in-bounds)
        float4 av = *(const float4*)(A + (size_t)(row0 + arow) * K + k0 + acol);
        As[acol + 0][arow] = av.x;
        As[acol + 1][arow] = av.y;
        As[acol + 2][arow] = av.z;
        As[acol + 3][arow] = av.w;
        // load B tile (guard N)
        float4 bv = make_float4(0.f, 0.f, 0.f, 0.f);
        const int gcol = col0 + bcol;
        if (gcol < N)
            bv = *(const float4*)(B + (size_t)(k0 + brow) * N + gcol);
        *(float4*)&Bs[brow][bcol] = bv;
        __syncthreads();

#pragma unroll
        for (int kk = 0; kk < 8; kk++) {
            float4 a0 = *(const float4*)&As[kk][ty * 8];
            float4 a1 = *(const float4*)&As[kk][ty * 8 + 4];
            float4 b0 = *(const float4*)&Bs[kk][tx * 8];
            float4 b1 = *(const float4*)&Bs[kk][tx * 8 + 4];
            const float ra[8] = {a0.x, a0.y, a0.z, a0.w, a1.x, a1.y, a1.z, a1.w};
            const float rb[8] = {b0.x, b0.y, b0.z, b0.w, b1.x, b1.y, b1.z, b1.w};
#pragma unroll
            for (int i = 0; i < 8; i++)
#pragma unroll
                for (int j = 0; j < 8; j++)
                    acc[i][j] = fmaf(ra[i], rb[j], acc[i][j]);
        }
        __syncthreads();
    }

#pragma unroll
    for (int i = 0; i < 8; i++) {
        const int grow = row0 + ty * 8 + i;
#pragma unroll
        for (int j4 = 0; j4 < 2; j4++) {
            const int gcol = col0 + tx * 8 + j4 * 4;
            if (gcol < N) {
                float4 v = make_float4(acc[i][j4 * 4 + 0], acc[i][j4 * 4 + 1],
                                       acc[i][j4 * 4 + 2], acc[i][j4 * 4 + 3]);
                *(float4*)(C + (size_t)grow * N + gcol) = v;
            }
        }
    }
}

// ---------------------------------------------------------------------------
// RMSNorm over 512 latent dims: out = x * rsqrt(mean(x^2)+eps) * w
// One block (128 threads) per token; input rows are the first 512 of g_kv[576].
// ---------------------------------------------------------------------------
__global__ __launch_bounds__(128)
void rmsnorm_kernel(const float* __restrict__ kv, const float* __restrict__ w,
                    float* __restrict__ out)
{
    __shared__ float red[4];
    const int tok = blockIdx.x;
    const int t = threadIdx.x;
    const float* row = kv + (size_t)tok * 576;
    float v[4];
    float s = 0.0f;
#pragma unroll
    for (int u = 0; u < 4; u++) {
        v[u] = row[t + u * 128];
        s = fmaf(v[u], v[u], s);
    }
#pragma unroll
    for (int off = 16; off > 0; off >>= 1)
        s += __shfl_down_sync(0xffffffffu, s, off);
    if ((t & 31) == 0) red[t >> 5] = s;
    __syncthreads();
    const float tot = red[0] + red[1] + red[2] + red[3];
    const float r = rsqrtf(tot * (1.0f / 512.0f) + 1e-6f);
    float* orow = out + (size_t)tok * 512;
#pragma unroll
    for (int u = 0; u < 4; u++) {
        const int idx = t + u * 128;
        orow[idx] = v[u] * r * w[idx];
    }
}

// ---------------------------------------------------------------------------
// RoPE on q_pe (dims 64..127 of each head), in place. grid=T, block=512 (16h x 32 pairs)
// ---------------------------------------------------------------------------
__global__ __launch_bounds__(512)
void rope_q_kernel(float* __restrict__ q)
{
    const int tok = blockIdx.x;
    const int h = threadIdx.x >> 5;
    const int i = threadIdx.x & 31;
    const int s = tok & (SEQ - 1);
    const float e = (float)(2 * i) * (1.0f / 64.0f);
    const float freq = 1.0f / powf(10000.0f, e);
    const float ang = (float)s * freq;
    float sn, c;
    sincosf(ang, &sn, &c);
    float* base = q + ((size_t)tok * 16 + h) * 128 + 64;
    const float x1 = base[2 * i];
    const float x2 = base[2 * i + 1];
    base[2 * i]     = x1 * c - x2 * sn;
    base[2 * i + 1] = x2 * c + x1 * sn;
}

// RoPE on k_pe (cols 512..575 of raw kv), written to g_kpe[T,64]. grid=T, block=32
__global__ __launch_bounds__(32)
void rope_k_kernel(const float* __restrict__ kv, float* __restrict__ kpe)
{
    const int tok = blockIdx.x;
    const int i = threadIdx.x;
    const int s = tok & (SEQ - 1);
    const float e = (float)(2 * i) * (1.0f / 64.0f);
    const float freq = 1.0f / powf(10000.0f, e);
    const float ang = (float)s * freq;
    float sn, c;
    sincosf(ang, &sn, &c);
    const float* src = kv + (size_t)tok * 576 + 512;
    const float x1 = src[2 * i];
    const float x2 = src[2 * i + 1];
    kpe[(size_t)tok * 64 + 2 * i]     = x1 * c - x2 * sn;
    kpe[(size_t)tok * 64 + 2 * i + 1] = x2 * c + x1 * sn;
}

// ---------------------------------------------------------------------------
// Flash attention (causal), fp32. Tiles: 64 q-rows x 64 kv-rows, d=128.
// grid = (S/64, H, B), block = 256 threads.
//   K row = [k_nope(64 dims from kvdec) | roped k_pe(64 dims)]
//   V row = kvdec dims 64..191
// ---------------------------------------------------------------------------
#define QPAD 132
#define PPAD 68
#define FLASH_SMEM ((3 * 64 * QPAD + 64 * PPAD + 3 * 64) * 4)

__global__ __launch_bounds__(256)
void flash_kernel(const float* __restrict__ q, const float* __restrict__ kvdec,
                  const float* __restrict__ kpe, float* __restrict__ o)
{
    extern __shared__ float sm[];
    float* Qs = sm;                       // 64 x QPAD
    float* Ks = Qs + 64 * QPAD;           // 64 x QPAD
    float* Vs = Ks + 64 * QPAD;           // 64 x QPAD
    float* Ps = Vs + 64 * QPAD;           // 64 x PPAD
    float* rm = Ps + 64 * PPAD;           // 64
    float* rl = rm + 64;                  // 64
    float* rf = rl + 64;                  // 64

    const int t  = threadIdx.x;
    const int qb = blockIdx.x;
    const int h  = blockIdx.y;
    const int b  = blockIdx.z;
    const int q0 = qb * 64;
    const float scale = 0.08838834764831845f;  // 1/sqrt(128)

    // Load + pre-scale Q tile
    for (int i = t; i < 64 * 128; i += 256) {
        const int r = i >> 7, d = i & 127;
        Qs[r * QPAD + d] =
            q[(((size_t)(b * SEQ + q0 + r) * 16 + h) << 7) + d] * scale;
    }
    if (t < 64) { rm[t] = -1e30f; rl[t] = 0.0f; }

    float acc[4][8];
#pragma unroll
    for (int i = 0; i < 4; i++)
#pragma unroll
        for (int j = 0; j < 8; j++) acc[i][j] = 0.0f;

    const int tr = t >> 4;   // 0..15  (score rows tr*4..tr*4+3)
    const int tc = t & 15;   // 0..15  (score cols tc*4..; out cols tc*8..)

    for (int kt = 0; kt <= qb; kt++) {
        __syncthreads();   // protect Qs (first iter) / Ks,Vs,Ps reuse
        const int k0 = kt * 64;
        for (int i = t; i < 64 * 128; i += 256) {
            const int r = i >> 7, d = i & 127;
            const size_t tok = (size_t)(b * SEQ + k0 + r);
            const float* kvrow = kvdec + (tok * 16 + h) * 192;
            Ks[r * QPAD + d] = (d < 64) ? kvrow[d] : kpe[tok * 64 + (d - 64)];
            Vs[r * QPAD + d] = kvrow[64 + d];
        }
        __syncthreads();

        // scores: 4x4 patch per thread over d=128
        float s4[4][4];
#pragma unroll
        for (int i = 0; i < 4; i++)
#pragma unroll
            for (int j = 0; j < 4; j++) s4[i][j] = 0.0f;

#pragma unroll 4
        for (int d4 = 0; d4 < 32; d4++) {
            float4 qv[4], kv4[4];
#pragma unroll
            for (int i = 0; i < 4; i++)
                qv[i] = *(const float4*)&Qs[(tr * 4 + i) * QPAD + d4 * 4];
#pragma unroll
            for (int j = 0; j < 4; j++)
                kv4[j] = *(const float4*)&Ks[(tc * 4 + j) * QPAD + d4 * 4];
#pragma unroll
            for (int i = 0; i < 4; i++)
#pragma unroll
                for (int j = 0; j < 4; j++) {
                    s4[i][j] = fmaf(qv[i].x, kv4[j].x, s4[i][j]);
                    s4[i][j] = fmaf(qv[i].y, kv4[j].y, s4[i][j]);
                    s4[i][j] = fmaf(qv[i].z, kv4[j].z, s4[i][j]);
                    s4[i][j] = fmaf(qv[i].w, kv4[j].w, s4[i][j]);
                }
        }

        if (kt == qb) {  // diagonal tile: causal mask (strictly upper)
#pragma unroll
            for (int i = 0; i < 4; i++)
#pragma unroll
                for (int j = 0; j < 4; j++)
                    if (tc * 4 + j > tr * 4 + i) s4[i][j] = -1e30f;
        }
#pragma unroll
        for (int i = 0; i < 4; i++)
#pragma unroll
            for (int j = 0; j < 4; j++)
                Ps[(tr * 4 + i) * PPAD + tc * 4 + j] = s4[i][j];
        __syncthreads();

        // online softmax: one thread per row
        if (t < 64) {
            const float mold = rm[t];
            float mx = mold;
#pragma unroll 8
            for (int c = 0; c < 64; c++) mx = fmaxf(mx, Ps[t * PPAD + c]);
            const float f = __expf(mold - mx);
            float sum = 0.0f;
#pragma unroll 8
            for (int c = 0; c < 64; c++) {
                const float p = __expf(Ps[t * PPAD + c] - mx);
                Ps[t * PPAD + c] = p;
                sum += p;
            }
            rm[t] = mx;
            rl[t] = rl[t] * f + sum;
            rf[t] = f;
        }
        __syncthreads();

        // rescale accumulators and add P @ V  (4 rows x 8 cols per thread)
        float fr[4];
#pragma unroll
        for (int i = 0; i < 4; i++) fr[i] = rf[tr * 4 + i];
#pragma unroll
        for (int i = 0; i < 4; i++)
#pragma unroll
            for (int j = 0; j < 8; j++) acc[i][j] *= fr[i];

        for (int k4 = 0; k4 < 16; k4++) {
            float4 p4[4];
#pragma unroll
            for (int i = 0; i < 4; i++)
                p4[i] = *(const float4*)&Ps[(tr * 4 + i) * PPAD + k4 * 4];
#pragma unroll
            for (int kk = 0; kk < 4; kk++) {
                const int k = k4 * 4 + kk;
                const float4 v0 = *(const float4*)&Vs[k * QPAD + tc * 8];
                const float4 v1 = *(const float4*)&Vs[k * QPAD + tc * 8 + 4];
                const float vv[8] = {v0.x, v0.y, v0.z, v0.w, v1.x, v1.y, v1.z, v1.w};
#pragma unroll
                for (int i = 0; i < 4; i++) {
                    const float p = (kk == 0) ? p4[i].x
                                  : (kk == 1) ? p4[i].y
                                  : (kk == 2) ? p4[i].z
                                              : p4[i].w;
#pragma unroll
                    for (int j = 0; j < 8; j++)
                        acc[i][j] = fmaf(p, vv[j], acc[i][j]);
                }
            }
        }
    }

    // epilogue: normalize by l and write
#pragma unroll
    for (int i = 0; i < 4; i++) {
        const float inv = 1.0f / rl[tr * 4 + i];
        const size_t base =
            (((size_t)(b * SEQ + q0 + tr * 4 + i) * 16 + h) << 7) + tc * 8;
        float4 o0 = make_float4(acc[i][0] * inv, acc[i][1] * inv,
                                acc[i][2] * inv, acc[i][3] * inv);
        float4 o1 = make_float4(acc[i][4] * inv, acc[i][5] * inv,
                                acc[i][6] * inv, acc[i][7] * inv);
        *(float4*)(o + base)     = o0;
        *(float4*)(o + base + 4) = o1;
    }
}

// ---------------------------------------------------------------------------
// Launch
// ---------------------------------------------------------------------------
extern "C" void kernel_launch(void* const* d_in, const int* in_sizes, int n_in,
                              void* d_out, int out_size)
{
    (void)in_sizes; (void)n_in; (void)out_size;
    const float* x          = (const float*)d_in[0];
    const float* w_query    = (const float*)d_in[1];
    const float* wkv_a      = (const float*)d_in[2];
    const float* wkv_b      = (const float*)d_in[3];
    const float* kv_norm_w  = (const float*)d_in[4];
    const float* out_proj_w = (const float*)d_in[5];
    float* out = (float*)d_out;

    float *q, *kv, *kvc, *kpe, *kvdec, *attn;
    cudaGetSymbolAddress((void**)&q,     g_q);
    cudaGetSymbolAddress((void**)&kv,    g_kv);
    cudaGetSymbolAddress((void**)&kvc,   g_kvc);
    cudaGetSymbolAddress((void**)&kpe,   g_kpe);
    cudaGetSymbolAddress((void**)&kvdec, g_kvdec);
    cudaGetSymbolAddress((void**)&attn,  g_attn);

    // q = x @ w_query             [4096,2048] = [4096,2048]@[2048,2048]
    sgemm_kernel<<<dim3(16, 32), 256>>>(x, w_query, q, TOKS, 2048, 2048);
    // kv = x @ wkv_a              [4096,576]  = [4096,2048]@[2048,576]
    sgemm_kernel<<<dim3(5, 32), 256>>>(x, wkv_a, kv, TOKS, 576, 2048);
    // rope q_pe in place
    rope_q_kernel<<<TOKS, 512>>>(q);
    // rmsnorm latent
    rmsnorm_kernel<<<TOKS, 128>>>(kv, kv_norm_w, kvc);
    // rope k_pe
    rope_k_kernel<<<TOKS, 32>>>(kv, kpe);
    // kv_dec = c @ wkv_b          [4096,3072] = [4096,512]@[512,3072]
    sgemm_kernel<<<dim3(24, 32), 256>>>(kvc, wkv_b, kvdec, TOKS, 3072, 512);
    // causal flash attention
    cudaFuncSetAttribute(flash_kernel,
                         cudaFuncAttributeMaxDynamicSharedMemorySize, FLASH_SMEM);
    flash_kernel<<<dim3(SEQ / 64, 16, 2), 256, FLASH_SMEM>>>(q, kvdec, kpe, attn);
    // out = attn @ out_proj_w     [4096,2048] = [4096,2048]@[2048,2048]
    sgemm_kernel<<<dim3(16, 32), 256>>>(attn, out_proj_w, out, TOKS, 2048, 2048);
}

// round 4
// speedup vs baseline: 3.8813x; 3.8813x over previous
#include <cuda_runtime.h>
#include <math.h>
#include <stdint.h>

// B=2, S=2048, T=4096, D_IN=2048, H=16, QK_HEAD=128 (64 nope + 64 rope),
// V_HEAD=128, KV_RANK=512, D_OUT=2048
#define TOKS 4096
#define SEQ  2048

// ---------------------------------------------------------------------------
// Scratch
// ---------------------------------------------------------------------------
__device__ float g_q[(size_t)TOKS * 2048];
__device__ float g_kv[(size_t)TOKS * 576];
__device__ float g_kvc[(size_t)TOKS * 512];
__device__ float g_kpe[(size_t)TOKS * 64];
__device__ float g_kvdec[(size_t)TOKS * 3072];
__device__ float g_attn[(size_t)TOKS * 2048];

// ---------------------------------------------------------------------------
// Helpers: tf32 convert, mma, cp.async
// ---------------------------------------------------------------------------
__device__ __forceinline__ uint32_t f2tf(float x) {
    uint32_t u;
    asm("cvt.rna.tf32.f32 %0, %1;" : "=r"(u) : "f"(x));
    return u;
}

__device__ __forceinline__ void mma_tf32(float* d, const uint32_t* a, const uint32_t* b) {
    asm volatile(
        "mma.sync.aligned.m16n8k8.row.col.f32.tf32.tf32.f32 "
        "{%0,%1,%2,%3}, {%4,%5,%6,%7}, {%8,%9}, {%0,%1,%2,%3};\n"
        : "+f"(d[0]), "+f"(d[1]), "+f"(d[2]), "+f"(d[3])
        : "r"(a[0]), "r"(a[1]), "r"(a[2]), "r"(a[3]), "r"(b[0]), "r"(b[1]));
}

__device__ __forceinline__ void cp_async16(void* smem_ptr, const void* gptr) {
    uint32_t saddr = (uint32_t)__cvta_generic_to_shared(smem_ptr);
    asm volatile("cp.async.cg.shared.global [%0], [%1], 16;\n"
                 :: "r"(saddr), "l"(gptr) : "memory");
}
__device__ __forceinline__ void cp_commit() {
    asm volatile("cp.async.commit_group;\n" ::: "memory");
}
template <int N>
__device__ __forceinline__ void cp_wait() {
    asm volatile("cp.async.wait_group %0;\n" :: "n"(N) : "memory");
}

// ---------------------------------------------------------------------------
// TF32 GEMM: C[M,N] = A[M,K] @ B[K,N], row-major fp32 in/out.
// BM=128, BN=128, BK=32. 256 threads = 8 warps, warp tile 64x32.
// As: [128][36] (stride%32==4 -> conflict-free A frags)
// Bs: [32][136] (stride%32==8 -> conflict-free B frags), no transpose needed.
// Requires M%128==0, K%32==0, N%4==0 (N tail guarded).
// ---------------------------------------------------------------------------
#define G_ASTR 36
#define G_BSTR 136
#define G_ABUF (128 * G_ASTR)
#define G_BBUF (32 * G_BSTR)
#define GEMM_SMEM ((2 * G_ABUF + 2 * G_BBUF) * 4)

__device__ __forceinline__ void gemm_stage(const float* __restrict__ A,
                                           const float* __restrict__ B,
                                           float* As, float* Bs,
                                           int row0, int col0, int k0,
                                           int K, int N, int t)
{
#pragma unroll
    for (int i = 0; i < 4; i++) {           // A: 128x32 = 1024 16B chunks
        const int c = t + i * 256;
        const int r = c >> 3, kc = (c & 7) * 4;
        cp_async16(As + r * G_ASTR + kc, A + (size_t)(row0 + r) * K + k0 + kc);
    }
#pragma unroll
    for (int i = 0; i < 4; i++) {           // B: 32x128 = 1024 16B chunks
        const int c = t + i * 256;
        const int r = c >> 5, nc = (c & 31) * 4;
        const int col = col0 + nc;
        if (col + 3 < N)
            cp_async16(Bs + r * G_BSTR + nc, B + (size_t)(k0 + r) * N + col);
        else
            *(float4*)&Bs[r * G_BSTR + nc] = make_float4(0.f, 0.f, 0.f, 0.f);
    }
}

__global__ __launch_bounds__(256)
void gemm_tf32(const float* __restrict__ A, const float* __restrict__ B,
               float* __restrict__ C, int M, int N, int K)
{
    extern __shared__ float sm[];
    float* As0 = sm;
    float* As1 = sm + G_ABUF;
    float* Bs0 = sm + 2 * G_ABUF;
    float* Bs1 = sm + 2 * G_ABUF + G_BBUF;

    const int t = threadIdx.x;
    const int lane = t & 31, wid = t >> 5;
    const int g = lane >> 2, tig = lane & 3;
    const int wm = wid >> 2;      // 0..1 -> 64 rows
    const int wn = wid & 3;       // 0..3 -> 32 cols
    const int row0 = blockIdx.y * 128;
    const int col0 = blockIdx.x * 128;

    float acc[4][4][4];
#pragma unroll
    for (int mt = 0; mt < 4; mt++)
#pragma unroll
        for (int nt = 0; nt < 4; nt++)
#pragma unroll
            for (int i = 0; i < 4; i++) acc[mt][nt][i] = 0.f;

    const int nkt = K >> 5;
    gemm_stage(A, B, As0, Bs0, row0, col0, 0, K, N, t);
    cp_commit();

    for (int kt = 0; kt < nkt; kt++) {
        float* Asb = (kt & 1) ? As1 : As0;
        float* Bsb = (kt & 1) ? Bs1 : Bs0;
        if (kt + 1 < nkt) {
            gemm_stage(A, B, (kt & 1) ? As0 : As1, (kt & 1) ? Bs0 : Bs1,
                       row0, col0, (kt + 1) << 5, K, N, t);
            cp_commit();
            cp_wait<1>();
        } else {
            cp_wait<0>();
        }
        __syncthreads();

#pragma unroll
        for (int ks = 0; ks < 4; ks++) {
            uint32_t af[4][4], bf[4][2];
#pragma unroll
            for (int mt = 0; mt < 4; mt++) {
                const float* ap = Asb + (wm * 64 + mt * 16) * G_ASTR + ks * 8;
                af[mt][0] = f2tf(ap[(g)     * G_ASTR + tig]);
                af[mt][1] = f2tf(ap[(g + 8) * G_ASTR + tig]);
                af[mt][2] = f2tf(ap[(g)     * G_ASTR + tig + 4]);
                af[mt][3] = f2tf(ap[(g + 8) * G_ASTR + tig + 4]);
            }
#pragma unroll
            for (int nt = 0; nt < 4; nt++) {
                const float* bp = Bsb + (ks * 8) * G_BSTR + wn * 32 + nt * 8 + g;
                bf[nt][0] = f2tf(bp[tig * G_BSTR]);
                bf[nt][1] = f2tf(bp[(tig + 4) * G_BSTR]);
            }
#pragma unroll
            for (int mt = 0; mt < 4; mt++)
#pragma unroll
                for (int nt = 0; nt < 4; nt++)
                    mma_tf32(acc[mt][nt], af[mt], bf[nt]);
        }
        __syncthreads();
    }

#pragma unroll
    for (int mt = 0; mt < 4; mt++) {
        const int gr0 = row0 + wm * 64 + mt * 16 + g;
#pragma unroll
        for (int nt = 0; nt < 4; nt++) {
            const int gc = col0 + wn * 32 + nt * 8 + 2 * tig;
            if (gc < N) {
                *(float2*)(C + (size_t)gr0 * N + gc) =
                    make_float2(acc[mt][nt][0], acc[mt][nt][1]);
                *(float2*)(C + (size_t)(gr0 + 8) * N + gc) =
                    make_float2(acc[mt][nt][2], acc[mt][nt][3]);
            }
        }
    }
}

// ---------------------------------------------------------------------------
// RMSNorm over 512 latent dims
// ---------------------------------------------------------------------------
__global__ __launch_bounds__(128)
void rmsnorm_kernel(const float* __restrict__ kv, const float* __restrict__ w,
                    float* __restrict__ out)
{
    __shared__ float red[4];
    const int tok = blockIdx.x;
    const int t = threadIdx.x;
    const float* row = kv + (size_t)tok * 576;
    float v[4];
    float s = 0.0f;
#pragma unroll
    for (int u = 0; u < 4; u++) {
        v[u] = row[t + u * 128];
        s = fmaf(v[u], v[u], s);
    }
#pragma unroll
    for (int off = 16; off > 0; off >>= 1)
        s += __shfl_down_sync(0xffffffffu, s, off);
    if ((t & 31) == 0) red[t >> 5] = s;
    __syncthreads();
    const float tot = red[0] + red[1] + red[2] + red[3];
    const float r = rsqrtf(tot * (1.0f / 512.0f) + 1e-6f);
    float* orow = out + (size_t)tok * 512;
#pragma unroll
    for (int u = 0; u < 4; u++) {
        const int idx = t + u * 128;
        orow[idx] = v[u] * r * w[idx];
    }
}

// ---------------------------------------------------------------------------
// RoPE
// ---------------------------------------------------------------------------
__global__ __launch_bounds__(512)
void rope_q_kernel(float* __restrict__ q)
{
    const int tok = blockIdx.x;
    const int h = threadIdx.x >> 5;
    const int i = threadIdx.x & 31;
    const int s = tok & (SEQ - 1);
    const float e = (float)(2 * i) * (1.0f / 64.0f);
    const float freq = 1.0f / powf(10000.0f, e);
    float sn, c;
    sincosf((float)s * freq, &sn, &c);
    float* base = q + ((size_t)tok * 16 + h) * 128 + 64;
    const float x1 = base[2 * i];
    const float x2 = base[2 * i + 1];
    base[2 * i]     = x1 * c - x2 * sn;
    base[2 * i + 1] = x2 * c + x1 * sn;
}

__global__ __launch_bounds__(32)
void rope_k_kernel(const float* __restrict__ kv, float* __restrict__ kpe)
{
    const int tok = blockIdx.x;
    const int i = threadIdx.x;
    const int s = tok & (SEQ - 1);
    const float e = (float)(2 * i) * (1.0f / 64.0f);
    const float freq = 1.0f / powf(10000.0f, e);
    float sn, c;
    sincosf((float)s * freq, &sn, &c);
    const float* src = kv + (size_t)tok * 576 + 512;
    const float x1 = src[2 * i];
    const float x2 = src[2 * i + 1];
    kpe[(size_t)tok * 64 + 2 * i]     = x1 * c - x2 * sn;
    kpe[(size_t)tok * 64 + 2 * i + 1] = x2 * c + x1 * sn;
}

// ---------------------------------------------------------------------------
// Flash attention (causal) with TF32 mma. 128 q-rows x 64 kv-rows, d=128.
// 256 threads = 8 warps. Scores: warp tile 32x32 (wm=wid>>1, wn=wid&1).
// PV: warp tile 32x64 (same row bands).
// ---------------------------------------------------------------------------
#define FQ 128
#define FKEY 64
#define QSTR 132       // %32==4
#define KSTR 132
#define VSTR 136       // %32==8
#define PSTR 68        // %32==4
#define FLASH_SMEM ((FQ*QSTR + FKEY*KSTR + FKEY*VSTR + FQ*PSTR + 3*FQ) * 4)

__global__ __launch_bounds__(256)
void flash_mma_kernel(const float* __restrict__ q, const float* __restrict__ kvdec,
                      const float* __restrict__ kpe, float* __restrict__ o)
{
    extern __shared__ float sm[];
    float* Qs = sm;                       // [128][132]
    float* Ks = Qs + FQ * QSTR;           // [64][132]
    float* Vs = Ks + FKEY * KSTR;         // [64][136]
    float* Ps = Vs + FKEY * VSTR;         // [128][68]
    float* rm = Ps + FQ * PSTR;
    float* rl = rm + FQ;
    float* rf = rl + FQ;

    const int t = threadIdx.x;
    const int lane = t & 31, wid = t >> 5;
    const int g = lane >> 2, tig = lane & 3;
    const int wm = wid >> 1;   // 0..3: 32-row band
    const int wn = wid & 1;    // 0..1
    const int qb = blockIdx.x, h = blockIdx.y, b = blockIdx.z;
    const int q0 = qb * FQ;
    const float scale = 0.08838834764831845f;  // 1/sqrt(128)

    // stage Q (pre-scaled)
    for (int c = t; c < FQ * 32; c += 256) {
        const int r = c >> 5, dc = (c & 31) * 4;
        float4 v = *(const float4*)(q + (((size_t)(b * SEQ + q0 + r) * 16 + h) << 7) + dc);
        v.x *= scale; v.y *= scale; v.z *= scale; v.w *= scale;
        *(float4*)&Qs[r * QSTR + dc] = v;
    }
    if (t < FQ) { rm[t] = -1e30f; rl[t] = 0.f; }

    float oacc[2][8][4];
#pragma unroll
    for (int mt = 0; mt < 2; mt++)
#pragma unroll
        for (int nt = 0; nt < 8; nt++)
#pragma unroll
            for (int i = 0; i < 4; i++) oacc[mt][nt][i] = 0.f;

    const int nkt = 2 * (qb + 1);
    for (int kt = 0; kt < nkt; kt++) {
        __syncthreads();
        const int k0 = kt * FKEY;
        // stage K (nope|rope) and V
        for (int c = t; c < FKEY * 32; c += 256) {
            const int r = c >> 5, dc = (c & 31) * 4;
            const size_t tok = (size_t)(b * SEQ + k0 + r);
            const float* kvrow = kvdec + (tok * 16 + h) * 192;
            float4 kv4 = (dc < 64) ? *(const float4*)(kvrow + dc)
                                   : *(const float4*)(kpe + tok * 64 + (dc - 64));
            *(float4*)&Ks[r * KSTR + dc] = kv4;
            *(float4*)&Vs[r * VSTR + dc] = *(const float4*)(kvrow + 64 + dc);
        }
        __syncthreads();

        // scores (warp: rows wm*32..+32, cols wn*32..+32)
        float sacc[2][4][4];
#pragma unroll
        for (int mt = 0; mt < 2; mt++)
#pragma unroll
            for (int nt = 0; nt < 4; nt++)
#pragma unroll
                for (int i = 0; i < 4; i++) sacc[mt][nt][i] = 0.f;

#pragma unroll
        for (int ks = 0; ks < 16; ks++) {
            uint32_t af[2][4], bf[4][2];
#pragma unroll
            for (int mt = 0; mt < 2; mt++) {
                const float* ap = Qs + (wm * 32 + mt * 16) * QSTR + ks * 8;
                af[mt][0] = f2tf(ap[(g)     * QSTR + tig]);
                af[mt][1] = f2tf(ap[(g + 8) * QSTR + tig]);
                af[mt][2] = f2tf(ap[(g)     * QSTR + tig + 4]);
                af[mt][3] = f2tf(ap[(g + 8) * QSTR + tig + 4]);
            }
#pragma unroll
            for (int nt = 0; nt < 4; nt++) {
                const float* bp = Ks + (wn * 32 + nt * 8 + g) * KSTR + ks * 8;
                bf[nt][0] = f2tf(bp[tig]);
                bf[nt][1] = f2tf(bp[tig + 4]);
            }
#pragma unroll
            for (int mt = 0; mt < 2; mt++)
#pragma unroll
                for (int nt = 0; nt < 4; nt++)
                    mma_tf32(sacc[mt][nt], af[mt], bf[nt]);
        }

        // causal mask on the two diagonal-adjacent tiles
        if (kt >= nkt - 2) {
#pragma unroll
            for (int mt = 0; mt < 2; mt++)
#pragma unroll
                for (int nt = 0; nt < 4; nt++) {
                    const int row = q0 + wm * 32 + mt * 16 + g;
                    const int col = k0 + wn * 32 + nt * 8 + 2 * tig;
                    if (col     > row)     sacc[mt][nt][0] = -1e30f;
                    if (col + 1 > row)     sacc[mt][nt][1] = -1e30f;
                    if (col     > row + 8) sacc[mt][nt][2] = -1e30f;
                    if (col + 1 > row + 8) sacc[mt][nt][3] = -1e30f;
                }
        }
        // store scores
#pragma unroll
        for (int mt = 0; mt < 2; mt++)
#pragma unroll
            for (int nt = 0; nt < 4; nt++) {
                const int lr = wm * 32 + mt * 16 + g;
                const int lc = wn * 32 + nt * 8 + 2 * tig;
                *(float2*)&Ps[lr * PSTR + lc] =
                    make_float2(sacc[mt][nt][0], sacc[mt][nt][1]);
                *(float2*)&Ps[(lr + 8) * PSTR + lc] =
                    make_float2(sacc[mt][nt][2], sacc[mt][nt][3]);
            }
        __syncthreads();

        // online softmax: thread-per-row
        if (t < FQ) {
            const float mold = rm[t];
            float mx = mold;
#pragma unroll 8
            for (int c = 0; c < FKEY; c++) mx = fmaxf(mx, Ps[t * PSTR + c]);
            const float f = __expf(mold - mx);
            float sum = 0.f;
#pragma unroll 8
            for (int c = 0; c < FKEY; c++) {
                const float p = __expf(Ps[t * PSTR + c] - mx);
                Ps[t * PSTR + c] = p;
                sum += p;
            }
            rm[t] = mx;
            rl[t] = rl[t] * f + sum;
            rf[t] = f;
        }
        __syncthreads();

        // rescale output accumulators, then O += P @ V
#pragma unroll
        for (int mt = 0; mt < 2; mt++) {
            const int rbase = wm * 32 + mt * 16;
            const float f0 = rf[rbase + g];
            const float f1 = rf[rbase + g + 8];
#pragma unroll
            for (int nt = 0; nt < 8; nt++) {
                oacc[mt][nt][0] *= f0; oacc[mt][nt][1] *= f0;
                oacc[mt][nt][2] *= f1; oacc[mt][nt][3] *= f1;
            }
        }
#pragma unroll
        for (int kk = 0; kk < 8; kk++) {
            uint32_t af[2][4], bf[8][2];
#pragma unroll
            for (int mt = 0; mt < 2; mt++) {
                const float* ap = Ps + (wm * 32 + mt * 16) * PSTR + kk * 8;
                af[mt][0] = f2tf(ap[(g)     * PSTR + tig]);
                af[mt][1] = f2tf(ap[(g + 8) * PSTR + tig]);
                af[mt][2] = f2tf(ap[(g)     * PSTR + tig + 4]);
                af[mt][3] = f2tf(ap[(g + 8) * PSTR + tig + 4]);
            }
#pragma unroll
            for (int nt = 0; nt < 8; nt++) {
                const float* bp = Vs + (kk * 8) * VSTR + wn * 64 + nt * 8 + g;
                bf[nt][0] = f2tf(bp[tig * VSTR]);
                bf[nt][1] = f2tf(bp[(tig + 4) * VSTR]);
            }
#pragma unroll
            for (int mt = 0; mt < 2; mt++)
#pragma unroll
                for (int nt = 0; nt < 8; nt++)
                    mma_tf32(oacc[mt][nt], af[mt], bf[nt]);
        }
    }

    __syncthreads();
    // epilogue: divide by l, write out
#pragma unroll
    for (int mt = 0; mt < 2; mt++) {
        const int rbase = wm * 32 + mt * 16;
        const float inv0 = 1.0f / rl[rbase + g];
        const float inv1 = 1.0f / rl[rbase + g + 8];
#pragma unroll
        for (int nt = 0; nt < 8; nt++) {
            const int col = wn * 64 + nt * 8 + 2 * tig;
            const size_t base0 =
                (((size_t)(b * SEQ + q0 + rbase + g) * 16 + h) << 7) + col;
            const size_t base1 =
                (((size_t)(b * SEQ + q0 + rbase + g + 8) * 16 + h) << 7) + col;
            *(float2*)(o + base0) =
                make_float2(oacc[mt][nt][0] * inv0, oacc[mt][nt][1] * inv0);
            *(float2*)(o + base1) =
                make_float2(oacc[mt][nt][2] * inv1, oacc[mt][nt][3] * inv1);
        }
    }
}

// ---------------------------------------------------------------------------
// Launch
// ---------------------------------------------------------------------------
extern "C" void kernel_launch(void* const* d_in, const int* in_sizes, int n_in,
                              void* d_out, int out_size)
{
    (void)in_sizes; (void)n_in; (void)out_size;
    const float* x          = (const float*)d_in[0];
    const float* w_query    = (const float*)d_in[1];
    const float* wkv_a      = (const float*)d_in[2];
    const float* wkv_b      = (const float*)d_in[3];
    const float* kv_norm_w  = (const float*)d_in[4];
    const float* out_proj_w = (const float*)d_in[5];
    float* out = (float*)d_out;

    float *q, *kv, *kvc, *kpe, *kvdec, *attn;
    cudaGetSymbolAddress((void**)&q,     g_q);
    cudaGetSymbolAddress((void**)&kv,    g_kv);
    cudaGetSymbolAddress((void**)&kvc,   g_kvc);
    cudaGetSymbolAddress((void**)&kpe,   g_kpe);
    cudaGetSymbolAddress((void**)&kvdec, g_kvdec);
    cudaGetSymbolAddress((void**)&attn,  g_attn);

    cudaFuncSetAttribute(gemm_tf32,
                         cudaFuncAttributeMaxDynamicSharedMemorySize, GEMM_SMEM);
    cudaFuncSetAttribute(flash_mma_kernel,
                         cudaFuncAttributeMaxDynamicSharedMemorySize, FLASH_SMEM);

    // q = x @ w_query             [4096,2048]
    gemm_tf32<<<dim3(16, 32), 256, GEMM_SMEM>>>(x, w_query, q, TOKS, 2048, 2048);
    // kv = x @ wkv_a              [4096,576]
    gemm_tf32<<<dim3(5, 32), 256, GEMM_SMEM>>>(x, wkv_a, kv, TOKS, 576, 2048);
    // rope q_pe in place
    rope_q_kernel<<<TOKS, 512>>>(q);
    // rmsnorm latent
    rmsnorm_kernel<<<TOKS, 128>>>(kv, kv_norm_w, kvc);
    // rope k_pe
    rope_k_kernel<<<TOKS, 32>>>(kv, kpe);
    // kv_dec = c @ wkv_b          [4096,3072]
    gemm_tf32<<<dim3(24, 32), 256, GEMM_SMEM>>>(kvc, wkv_b, kvdec, TOKS, 3072, 512);
    // causal flash attention (tf32 mma)
    flash_mma_kernel<<<dim3(SEQ / FQ, 16, 2), 256, FLASH_SMEM>>>(q, kvdec, kpe, attn);
    // out = attn @ out_proj_w     [4096,2048]
    gemm_tf32<<<dim3(16, 32), 256, GEMM_SMEM>>>(attn, out_proj_w, out, TOKS, 2048, 2048);
}